// round 8
// baseline (speedup 1.0000x reference)
#include <cuda_runtime.h>
#include <math.h>
#include <stdint.h>

#define BB  4
#define TT  1024
#define CC  1024
#define NH  16
#define NKVH 4
#define HD  64
#define BT  (BB*TT)
#define FFN 4096
#define CAD 32
#define VECH 12
#define QKVW 1536            // fused qkv row width

// ---------------- scratch ----------------------------------------------------
__device__ float g_xn  [BT*CC];
__device__ float g_qkv [(size_t)BT*QKVW];
__device__ float g_wqkv[QKVW*CC];
__device__ float g_y   [BT*CC];
__device__ float g_attn[BT*CC];
__device__ float g_cag [BT*CAD];
__device__ float g_cag2[BT*CAD];
__device__ float g_ca  [BT*CC];
__device__ float g_x1  [BT*CC];
__device__ float g_xm  [BT*CC];
__device__ float g_h   [(size_t)BT*FFN];
__device__ float g_h2  [(size_t)BT*FFN];
__device__ float g_gate[BT*CC];
__device__ float g_mlp [BT*CC];
__device__ float g_vit32[BT*CAD];
__device__ float g_vita[BT];
__device__ float g_vitb[BT];

// ---------------- helpers ----------------------------------------------------
__device__ __forceinline__ float geluf(float x){ return 0.5f*x*(1.0f+erff(x*0.70710678118654752f)); }
__device__ __forceinline__ float sigmf(float x){ return 1.0f/(1.0f+expf(-x)); }

// cheap split: hi = truncate-to-tf32(x) (bitmask), lo = x - hi (exact).
// mma HW truncates operands to tf32, so lo's low bits are dropped in-HW.
__device__ __forceinline__ void splitc(float x, float& hi, float& lo){
    hi = __uint_as_float(__float_as_uint(x) & 0xFFFFE000u);
    lo = x - hi;
}

__device__ __forceinline__ void mma_tf32(float* d, const float* a, const float* b){
    asm volatile("mma.sync.aligned.m16n8k8.row.col.f32.tf32.tf32.f32 "
        "{%0,%1,%2,%3}, {%4,%5,%6,%7}, {%8,%9}, {%0,%1,%2,%3};"
        : "+f"(d[0]), "+f"(d[1]), "+f"(d[2]), "+f"(d[3])
        : "r"(__float_as_uint(a[0])), "r"(__float_as_uint(a[1])),
          "r"(__float_as_uint(a[2])), "r"(__float_as_uint(a[3])),
          "r"(__float_as_uint(b[0])), "r"(__float_as_uint(b[1])));
}

__device__ __forceinline__ void cp_async16(float* smem_dst, const float* gsrc, bool pred){
    uint32_t s = (uint32_t)__cvta_generic_to_shared(smem_dst);
    int sz = pred ? 16 : 0;
    asm volatile("cp.async.cg.shared.global [%0], [%1], 16, %2;\n" :: "r"(s), "l"(gsrc), "r"(sz));
}
#define CP_COMMIT() asm volatile("cp.async.commit_group;\n" ::: "memory")
#define CP_WAIT1()  asm volatile("cp.async.wait_group 1;\n" ::: "memory")
#define CP_WAIT0()  asm volatile("cp.async.wait_group 0;\n" ::: "memory")

// ---------------- 3xTF32 pipelined NT GEMM (BM=128 BN=128 BK=32) -------------
// C[M,N] = A[M,K]*B[N,K]^T.  M%128==0, K%32==0, N guarded. ldc = row stride.
// 256 thr = 8 warps (4m x 2n); warp tile 32x64. cp.async double buffer.
#define GST 36
#define TILE_F (128*GST)
#define GEMM_SMEM (4*TILE_F*4)

template<int EPI>
__global__ void __launch_bounds__(256) gemm_tf32(const float* __restrict__ A,
                                                 const float* __restrict__ Bm,
                                                 float* __restrict__ Cm,
                                                 int M, int N, int K, int ldc)
{
    extern __shared__ float sm[];
    float* As[2] = { sm, sm + TILE_F };
    float* Bs[2] = { sm + 2*TILE_F, sm + 3*TILE_F };

    const int tid  = threadIdx.x;
    const int bm   = blockIdx.y * 128;
    const int bn   = blockIdx.x * 128;
    const int wid  = tid >> 5, lane = tid & 31;
    const int wm   = wid & 3, wn = wid >> 2;
    const int r    = lane >> 2;
    const int kq   = lane & 3;

    float acc[2][8][4];
    #pragma unroll
    for (int i = 0; i < 2; i++)
        #pragma unroll
        for (int j = 0; j < 8; j++)
            #pragma unroll
            for (int c = 0; c < 4; c++) acc[i][j][c] = 0.f;

    const int KT = K >> 5;

    {
        #pragma unroll
        for (int it = 0; it < 4; it++) {
            int g = tid + it*256;
            int m = g >> 3, kg = (g & 7) * 4;
            cp_async16(&As[0][m*GST + kg], &A[(size_t)(bm+m)*K + kg], true);
            cp_async16(&Bs[0][m*GST + kg], &Bm[(size_t)(bn+m)*K + kg], bn + m < N);
        }
        CP_COMMIT();
    }

    for (int kt = 0; kt < KT; kt++) {
        if (kt + 1 < KT) {
            int k0 = (kt+1) << 5;
            int nb = (kt+1) & 1;
            #pragma unroll
            for (int it = 0; it < 4; it++) {
                int g = tid + it*256;
                int m = g >> 3, kg = (g & 7) * 4;
                cp_async16(&As[nb][m*GST + kg], &A[(size_t)(bm+m)*K + k0 + kg], true);
                cp_async16(&Bs[nb][m*GST + kg], &Bm[(size_t)(bn+m)*K + k0 + kg], bn + m < N);
            }
            CP_COMMIT();
            CP_WAIT1();
        } else {
            CP_WAIT0();
        }
        __syncthreads();

        const float* Ab = As[kt & 1];
        const float* Bb = Bs[kt & 1];
        #pragma unroll
        for (int ch = 0; ch < 4; ch++) {
            const int kb = ch*8 + kq;
            float ah[2][4], al[2][4];
            #pragma unroll
            for (int mt = 0; mt < 2; mt++) {
                int row = wm*32 + mt*16 + r;
                splitc(Ab[row*GST + kb],       ah[mt][0], al[mt][0]);
                splitc(Ab[(row+8)*GST + kb],   ah[mt][1], al[mt][1]);
                splitc(Ab[row*GST + kb + 4],   ah[mt][2], al[mt][2]);
                splitc(Ab[(row+8)*GST + kb+4], ah[mt][3], al[mt][3]);
            }
            #pragma unroll
            for (int nt = 0; nt < 8; nt++) {
                int col = wn*64 + nt*8 + r;
                float bh[2], bl[2];
                splitc(Bb[col*GST + kb],     bh[0], bl[0]);
                splitc(Bb[col*GST + kb + 4], bh[1], bl[1]);
                #pragma unroll
                for (int mt = 0; mt < 2; mt++) {
                    mma_tf32(acc[mt][nt], ah[mt], bh);
                    mma_tf32(acc[mt][nt], ah[mt], bl);
                    mma_tf32(acc[mt][nt], al[mt], bh);
                }
            }
        }
        __syncthreads();
    }

    #pragma unroll
    for (int mt = 0; mt < 2; mt++) {
        int row0 = bm + wm*32 + mt*16 + r;
        #pragma unroll
        for (int nt = 0; nt < 8; nt++) {
            int col0 = bn + wn*64 + nt*8 + kq*2;
            #pragma unroll
            for (int c = 0; c < 4; c++) {
                int row = row0 + (c >= 2 ? 8 : 0);
                int col = col0 + (c & 1);
                if (col < N) {
                    float v = acc[mt][nt][c];
                    if (EPI == 1) { v = fmaxf(v, 0.f); v = v*v; }
                    else if (EPI == 2) { v = sigmf(v); }
                    else if (EPI == 3) { v = geluf(v); }
                    Cm[(size_t)row*ldc + col] = v;
                }
            }
        }
    }
}

// ---------------- pack w_q|w_k|w_v -> g_wqkv --------------------------------
__global__ void packqkv_k(const float* __restrict__ wq, const float* __restrict__ wk,
                          const float* __restrict__ wv, float* __restrict__ w)
{
    int i = blockIdx.x*256 + threadIdx.x;            // float4 index, total QKVW*CC/4
    if (i >= QKVW*CC/4) return;
    int row = i >> 8;                                 // /(CC/4)
    int c4  = i & 255;
    float4 v;
    if (row < 1024)       v = ((const float4*)wq)[row*256 + c4];
    else if (row < 1280)  v = ((const float4*)wk)[(row-1024)*256 + c4];
    else                  v = ((const float4*)wv)[(row-1280)*256 + c4];
    ((float4*)w)[i] = v;
}

// ---------------- rmsnorm ----------------------------------------------------
__global__ void rmsnorm_k(const float* __restrict__ in, float* __restrict__ out)
{
    __shared__ float red[256];
    int row = blockIdx.x;
    const float* r = in + (size_t)row*CC;
    float s = 0.f;
    for (int i = threadIdx.x; i < CC; i += 256) { float v = r[i]; s += v*v; }
    red[threadIdx.x] = s; __syncthreads();
    for (int st = 128; st > 0; st >>= 1) {
        if (threadIdx.x < st) red[threadIdx.x] += red[threadIdx.x+st];
        __syncthreads();
    }
    float scale = rsqrtf(red[0]/(float)CC + 1e-6f);
    for (int i = threadIdx.x; i < CC; i += 256) out[(size_t)row*CC + i] = r[i]*scale;
}

// ---------------- ve gate (v lives in fused qkv buffer) ----------------------
__global__ void gatve_k(const float* __restrict__ xn, const float* __restrict__ ve,
                        const float* __restrict__ wg, float* __restrict__ qkv)
{
    int bt = blockIdx.x;
    int tid = threadIdx.x;              // 0..255 = NKVH*HD
    int kv  = tid >> 6;
    float dot = 0.f;
    #pragma unroll
    for (int c = 0; c < VECH; c++) dot += xn[(size_t)bt*CC + c] * wg[kv*VECH + c];
    float gate = 3.0f * sigmf(dot);
    qkv[(size_t)bt*QKVW + 1280 + tid] += gate * ve[(size_t)bt*256 + tid];
}

// ---------------- rope + per-head rmsnorm * 1.2 ------------------------------
__global__ void ropenorm_k(float* __restrict__ base, const float* __restrict__ cs,
                           const float* __restrict__ sn, int nheads)
{
    int gw   = (blockIdx.x * blockDim.x + threadIdx.x) >> 5;
    int lane = threadIdx.x & 31;
    int total = BT * nheads;
    if (gw >= total) return;
    int bt = gw / nheads, h = gw % nheads;
    int t  = bt % TT;
    float* p = base + (size_t)bt*QKVW + h*HD;
    float x1 = p[lane], x2 = p[lane+32];
    float c = cs[t*32 + lane], s = sn[t*32 + lane];
    float o1 =  x1*c + x2*s;
    float o2 = -x1*s + x2*c;
    float ss = o1*o1 + o2*o2;
    #pragma unroll
    for (int m = 16; m > 0; m >>= 1) ss += __shfl_xor_sync(0xffffffffu, ss, m);
    float scale = rsqrtf(ss/64.f + 1e-6f) * 1.2f;
    p[lane]    = o1*scale;
    p[lane+32] = o2*scale;
}

// ---------------- flash attention with refine conv (round-1 proven) ----------
// Q at qkv+0, K at qkv+1024, V at qkv+1280, row stride QKVW. Y:[BT,NH,64].
__global__ void __launch_bounds__(256) flash_k(
    const float* __restrict__ QKV, const float* __restrict__ prev,
    const float* __restrict__ rw, const float* __restrict__ alphap,
    float* __restrict__ Y)
{
    extern __shared__ float sm[];
    float* Qs = sm;                 // 64*65
    float* Ks = Qs + 64*65;
    float* Vs = Ks + 64*65;
    float* Ps = Vs + 64*65;
    float* Pv = Ps + 64*65;         // 66*68
    int tid = threadIdx.x;
    int tx = tid & 15, ty = tid >> 4;
    int qb = blockIdx.x;
    int bh = blockIdx.y;            // b*NH + h
    int b = bh >> 4, h = bh & 15;
    int kvh = h >> 2;
    int q0 = qb*64;
    float alpha = alphap[0];
    float w9[9];
    #pragma unroll
    for (int i = 0; i < 9; i++) w9[i] = rw[h*9 + i];

    for (int i = tid; i < 64*16; i += 256) {
        int r = i >> 4, c4 = i & 15;
        float4 v4 = *(const float4*)&QKV[(size_t)(b*TT + q0 + r)*QKVW + h*HD + c4*4];
        Qs[r*65+c4*4+0]=v4.x; Qs[r*65+c4*4+1]=v4.y; Qs[r*65+c4*4+2]=v4.z; Qs[r*65+c4*4+3]=v4.w;
    }

    float m[4], l[4], o[4][4];
    #pragma unroll
    for (int i = 0; i < 4; i++) {
        m[i] = -1e30f; l[i] = 0.f;
        #pragma unroll
        for (int j = 0; j < 4; j++) o[i][j] = 0.f;
    }
    const float* pbase = prev + (size_t)bh*TT*TT;

    for (int kc = 0; kc <= qb; kc++) {
        int k0 = kc*64;
        for (int i = tid; i < 64*16; i += 256) {
            int r = i >> 4, c4 = i & 15;
            size_t base = (size_t)(b*TT + k0 + r)*QKVW + kvh*HD + c4*4;
            float4 k4 = *(const float4*)&QKV[1024 + base];
            Ks[r*65+c4*4+0]=k4.x; Ks[r*65+c4*4+1]=k4.y; Ks[r*65+c4*4+2]=k4.z; Ks[r*65+c4*4+3]=k4.w;
            float4 v4 = *(const float4*)&QKV[1280 + base];
            Vs[r*65+c4*4+0]=v4.x; Vs[r*65+c4*4+1]=v4.y; Vs[r*65+c4*4+2]=v4.z; Vs[r*65+c4*4+3]=v4.w;
        }
        for (int i = tid; i < 66*66; i += 256) {
            int r = i/66, c = i - r*66;
            int gq = q0-1+r, gk = k0-1+c;
            float val = 0.f;
            if (gq >= 0 && gq < TT && gk >= 0 && gk < TT) val = pbase[(size_t)gq*TT + gk];
            Pv[r*68+c] = val;
        }
        __syncthreads();

        float s[4][4];
        #pragma unroll
        for (int i = 0; i < 4; i++)
            #pragma unroll
            for (int j = 0; j < 4; j++) s[i][j] = 0.f;
        #pragma unroll 8
        for (int d = 0; d < 64; d++) {
            float a[4], bb[4];
            #pragma unroll
            for (int i = 0; i < 4; i++) a[i]  = Qs[(ty*4+i)*65 + d];
            #pragma unroll
            for (int j = 0; j < 4; j++) bb[j] = Ks[(tx*4+j)*65 + d];
            #pragma unroll
            for (int i = 0; i < 4; i++)
                #pragma unroll
                for (int j = 0; j < 4; j++) s[i][j] += a[i]*bb[j];
        }
        #pragma unroll
        for (int i = 0; i < 4; i++) {
            int lr = ty*4+i;
            #pragma unroll
            for (int j = 0; j < 4; j++) {
                int lc = tx*4+j;
                float cv = 0.f;
                #pragma unroll
                for (int di = 0; di < 3; di++)
                    #pragma unroll
                    for (int dj = 0; dj < 3; dj++)
                        cv += Pv[(lr+di)*68 + lc+dj] * w9[di*3+dj];
                float val = s[i][j]*0.125f + alpha*cv;
                if (k0+lc > q0+lr) val = -1e30f;
                s[i][j] = val;
            }
        }
        // online softmax
        float mn[4], corr[4];
        #pragma unroll
        for (int i = 0; i < 4; i++) {
            float rm = s[i][0];
            #pragma unroll
            for (int j = 1; j < 4; j++) rm = fmaxf(rm, s[i][j]);
            #pragma unroll
            for (int msk = 8; msk > 0; msk >>= 1)
                rm = fmaxf(rm, __shfl_xor_sync(0xffffffffu, rm, msk));
            mn[i] = fmaxf(m[i], rm);
            corr[i] = expf(m[i] - mn[i]);
        }
        #pragma unroll
        for (int i = 0; i < 4; i++) {
            float sum = 0.f;
            #pragma unroll
            for (int j = 0; j < 4; j++) { float p = expf(s[i][j] - mn[i]); s[i][j] = p; sum += p; }
            #pragma unroll
            for (int msk = 8; msk > 0; msk >>= 1)
                sum += __shfl_xor_sync(0xffffffffu, sum, msk);
            l[i] = l[i]*corr[i] + sum;
            m[i] = mn[i];
            #pragma unroll
            for (int j = 0; j < 4; j++) o[i][j] *= corr[i];
        }
        #pragma unroll
        for (int i = 0; i < 4; i++)
            #pragma unroll
            for (int j = 0; j < 4; j++) Ps[(ty*4+i)*65 + tx*4+j] = s[i][j];
        __syncthreads();
        #pragma unroll 8
        for (int kk = 0; kk < 64; kk++) {
            float a[4], bb[4];
            #pragma unroll
            for (int i = 0; i < 4; i++) a[i]  = Ps[(ty*4+i)*65 + kk];
            #pragma unroll
            for (int j = 0; j < 4; j++) bb[j] = Vs[kk*65 + tx*4+j];
            #pragma unroll
            for (int i = 0; i < 4; i++)
                #pragma unroll
                for (int j = 0; j < 4; j++) o[i][j] += a[i]*bb[j];
        }
        __syncthreads();
    }

    #pragma unroll
    for (int i = 0; i < 4; i++) {
        float inv = 1.f/l[i];
        #pragma unroll
        for (int j = 0; j < 4; j++)
            Y[((size_t)(b*TT + q0 + ty*4 + i)*NH + h)*HD + tx*4 + j] = o[i][j]*inv;
    }
}

// ---------------- CA channel conv (+gelu) ------------------------------------
__global__ void caconv_gelu_k(const float* __restrict__ g, const float* __restrict__ cw,
                              float* __restrict__ out)
{
    int idx = blockIdx.x*256 + threadIdx.x;
    if (idx >= BT*CAD) return;
    int c = idx & 31;
    int bt = idx >> 5;
    int t = bt & (TT-1);
    float w0 = cw[c*3], w1 = cw[c*3+1], w2 = cw[c*3+2];
    float xm1 = (t > 0)     ? g[idx-CAD] : 0.f;
    float x0  = g[idx];
    float xp1 = (t < TT-1)  ? g[idx+CAD] : 0.f;
    float h = x0 + 0.1f*(w0*xm1 + w1*x0 + w2*xp1);
    out[idx] = geluf(h);
}

// ---------------- fused 4-step FFN depthwise conv ----------------------------
__global__ void __launch_bounds__(256) ffnconv4_k(const float* __restrict__ in,
                                                  const float* __restrict__ cw,
                                                  float* __restrict__ out)
{
    __shared__ float sA[40*128];
    __shared__ float sB[40*128];
    const int tid = threadIdx.x;
    const int c0 = blockIdx.x * 128;
    const int t0 = blockIdx.y * 32;
    const int b  = blockIdx.z;
    const int c  = tid & 127;
    const int r0 = tid >> 7;

    for (int i = tid; i < 40*128; i += 256) {
        int rr = i >> 7, cc = i & 127;
        int t = t0 - 4 + rr;
        float val = 0.f;
        if (t >= 0 && t < TT) val = in[((size_t)(b*TT + t))*FFN + c0 + cc];
        sA[i] = val;
    }
    float w0 = cw[(c0+c)*3], w1 = cw[(c0+c)*3+1], w2 = cw[(c0+c)*3+2];
    __syncthreads();

    float* X = sA; float* Y2 = sB;
    #pragma unroll
    for (int it = 0; it < 4; it++) {
        for (int rr = r0; rr < 40; rr += 2) {
            int t = t0 - 4 + rr;
            float x0 = X[rr*128 + c];
            float xm = (rr > 0)  ? X[(rr-1)*128 + c] : 0.f;
            float xp = (rr < 39) ? X[(rr+1)*128 + c] : 0.f;
            float nv = x0 + 0.1f*(w0*xm + w1*x0 + w2*xp);
            if (t < 0 || t >= TT) nv = 0.f;
            Y2[rr*128 + c] = nv;
        }
        __syncthreads();
        float* tmp = X; X = Y2; Y2 = tmp;
    }
    for (int rr = 4 + r0; rr < 36; rr += 2) {
        int t = t0 - 4 + rr;
        out[((size_t)(b*TT + t))*FFN + c0 + c] = X[rr*128 + c];
    }
}

// ---------------- elementwise ------------------------------------------------
__global__ void x1_k(const float* __restrict__ x, const float* __restrict__ attn,
                     const float* __restrict__ ca, float* __restrict__ x1)
{
    size_t i = (size_t)blockIdx.x*256 + threadIdx.x;
    x1[i] = x[i] + attn[i]*(1.0f + 0.1f*tanhf(ca[i]));
}

__global__ void vitsm_k(const float* __restrict__ vin, float* __restrict__ vout)
{
    int idx = blockIdx.x*256 + threadIdx.x;
    if (idx >= BT) return;
    int b = idx >> 10, t = idx & (TT-1);
    const float* vb = vin + b*TT;
    float s = 0.f;
    #pragma unroll
    for (int o = -2; o <= 2; o++) {
        int tt = t + o;
        if (tt >= 0 && tt < TT) s += vb[tt];
    }
    s *= 0.2f;
    float v = 0.7f*vin[idx] + 0.3f*s;
    vout[idx] = (v > 0.3f) ? v : v*0.1f;
}

__global__ void final_k(const float* __restrict__ x1, const float* __restrict__ mlp,
                        const float* __restrict__ gate, const float* __restrict__ ca,
                        const float* __restrict__ vit, float* __restrict__ out)
{
    size_t i = (size_t)blockIdx.x*256 + threadIdx.x;
    int row = (int)(i >> 10);
    float m = mlp[i]*gate[i]*(1.0f + 0.1f*tanhf(ca[i]));
    out[i] = x1[i] + m*vit[row];
}

// ---------------- host -------------------------------------------------------
static void launch_gemm(const float* A, const float* B, float* C,
                        int M, int N, int K, int ldc, int epi)
{
    dim3 g((N+127)/128, M/128), b(256);
    switch (epi) {
        case 0: gemm_tf32<0><<<g,b,GEMM_SMEM>>>(A,B,C,M,N,K,ldc); break;
        case 1: gemm_tf32<1><<<g,b,GEMM_SMEM>>>(A,B,C,M,N,K,ldc); break;
        case 2: gemm_tf32<2><<<g,b,GEMM_SMEM>>>(A,B,C,M,N,K,ldc); break;
        default: gemm_tf32<3><<<g,b,GEMM_SMEM>>>(A,B,C,M,N,K,ldc); break;
    }
}

#define FLASH_SMEM ((4*64*65 + 66*68)*4)

extern "C" void kernel_launch(void* const* d_in, const int* in_sizes, int n_in,
                              void* d_out, int out_size)
{
    const float* x       = (const float*)d_in[0];
    const float* ve      = (const float*)d_in[1];
    const float* cosb    = (const float*)d_in[2];
    const float* sinb    = (const float*)d_in[3];
    const float* prev    = (const float*)d_in[4];
    const float* w_q     = (const float*)d_in[5];
    const float* w_k     = (const float*)d_in[6];
    const float* w_v     = (const float*)d_in[7];
    const float* w_o     = (const float*)d_in[8];
    const float* w_veg   = (const float*)d_in[9];
    const float* refw    = (const float*)d_in[10];
    const float* ralpha  = (const float*)d_in[11];
    const float* ca_pi   = (const float*)d_in[12];
    const float* ca_cw   = (const float*)d_in[13];
    const float* ca_po   = (const float*)d_in[14];
    const float* ffn_in  = (const float*)d_in[15];
    const float* ffn_cw  = (const float*)d_in[16];
    const float* ffn_out = (const float*)d_in[17];
    const float* ffn_gate= (const float*)d_in[18];
    const float* vit_w1  = (const float*)d_in[19];
    const float* vit_w2  = (const float*)d_in[20];
    float* out = (float*)d_out;

    static bool attr_done = false;
    if (!attr_done) {
        cudaFuncSetAttribute(gemm_tf32<0>, cudaFuncAttributeMaxDynamicSharedMemorySize, GEMM_SMEM);
        cudaFuncSetAttribute(gemm_tf32<1>, cudaFuncAttributeMaxDynamicSharedMemorySize, GEMM_SMEM);
        cudaFuncSetAttribute(gemm_tf32<2>, cudaFuncAttributeMaxDynamicSharedMemorySize, GEMM_SMEM);
        cudaFuncSetAttribute(gemm_tf32<3>, cudaFuncAttributeMaxDynamicSharedMemorySize, GEMM_SMEM);
        cudaFuncSetAttribute(flash_k, cudaFuncAttributeMaxDynamicSharedMemorySize, FLASH_SMEM);
        attr_done = true;
    }

    float *xn,*qkv,*wqkv,*y,*attn,*cag,*cag2,*ca,*x1,*xm,*h,*h2,*gate,*mlp,*vit32,*vita,*vitb;
    cudaGetSymbolAddress((void**)&xn,   g_xn);
    cudaGetSymbolAddress((void**)&qkv,  g_qkv);
    cudaGetSymbolAddress((void**)&wqkv, g_wqkv);
    cudaGetSymbolAddress((void**)&y,    g_y);
    cudaGetSymbolAddress((void**)&attn, g_attn);
    cudaGetSymbolAddress((void**)&cag,  g_cag);
    cudaGetSymbolAddress((void**)&cag2, g_cag2);
    cudaGetSymbolAddress((void**)&ca,   g_ca);
    cudaGetSymbolAddress((void**)&x1,   g_x1);
    cudaGetSymbolAddress((void**)&xm,   g_xm);
    cudaGetSymbolAddress((void**)&h,    g_h);
    cudaGetSymbolAddress((void**)&h2,   g_h2);
    cudaGetSymbolAddress((void**)&gate, g_gate);
    cudaGetSymbolAddress((void**)&mlp,  g_mlp);
    cudaGetSymbolAddress((void**)&vit32,g_vit32);
    cudaGetSymbolAddress((void**)&vita, g_vita);
    cudaGetSymbolAddress((void**)&vitb, g_vitb);

    // 0. pack qkv weights
    packqkv_k<<<(QKVW*CC/4 + 255)/256, 256>>>(w_q, w_k, w_v, wqkv);
    // 1. xn = rmsnorm(x)
    rmsnorm_k<<<BT, 256>>>(x, xn);
    // 2. fused qkv projection -> g_qkv [BT, 1536]
    launch_gemm(xn, wqkv, qkv, BT, QKVW, CC, QKVW, 0);
    // 3. ve gate (on v slice)
    gatve_k<<<BT, 256>>>(xn, ve, w_veg, qkv);
    // 4. rope + head rmsnorm
    ropenorm_k<<<(BT*NH)/8, 256>>>(qkv, cosb, sinb, NH);
    ropenorm_k<<<(BT*NKVH)/8, 256>>>(qkv + 1024, cosb, sinb, NKVH);
    // 5. flash attention with refine conv
    {
        dim3 g(TT/64, BB*NH);
        flash_k<<<g, 256, FLASH_SMEM>>>(qkv, prev, refw, ralpha, y);
    }
    // 6. attn_out
    launch_gemm(y, w_o, attn, BT, CC, CC, CC, 0);
    // 7. ca1 (on x)
    launch_gemm(x, ca_pi, cag, BT, CAD, CC, CAD, 0);
    caconv_gelu_k<<<(BT*CAD)/256, 256>>>(cag, ca_cw, cag2);
    launch_gemm(cag2, ca_po, ca, BT, CC, CAD, CC, 0);
    // 8. x1
    x1_k<<<(BT*CC)/256, 256>>>(x, attn, ca, x1);
    // 9. xm = rmsnorm(x1)
    rmsnorm_k<<<BT, 256>>>(x1, xm);
    // 10. FFN
    launch_gemm(xm, ffn_in, h, BT, FFN, CC, FFN, 1);
    {
        dim3 g(FFN/128, TT/32, BB);
        ffnconv4_k<<<g, 256>>>(h, ffn_cw, h2);
    }
    launch_gemm(xm, ffn_gate, gate, BT, CC, CC, CC, 2);
    launch_gemm(h2, ffn_out, mlp, BT, CC, FFN, CC, 0);
    // 11. ca2 (on x1)
    launch_gemm(x1, ca_pi, cag, BT, CAD, CC, CAD, 0);
    caconv_gelu_k<<<(BT*CAD)/256, 256>>>(cag, ca_cw, cag2);
    launch_gemm(cag2, ca_po, ca, BT, CC, CAD, CC, 0);
    // 12. vit path
    launch_gemm(x1, vit_w1, vit32, BT, CAD, CC, CAD, 3);
    launch_gemm(vit32, vit_w2, vita, BT, 1, CAD, 1, 2);
    vitsm_k<<<(BT+255)/256, 256>>>(vita, vitb);
    // 13. final
    final_k<<<(BT*CC)/256, 256>>>(x1, mlp, gate, ca, vitb, out);
}

// round 9
// speedup vs baseline: 1.5819x; 1.5819x over previous
#include <cuda_runtime.h>
#include <math.h>
#include <stdint.h>

#define BB  4
#define TT  1024
#define CC  1024
#define NH  16
#define NKVH 4
#define HD  64
#define BT  (BB*TT)
#define FFN 4096
#define CAD 32
#define VECH 12

// ---------------- scratch ----------------------------------------------------
__device__ float g_xn  [BT*CC];
__device__ float g_q   [BT*CC];
__device__ float g_k   [BT*NKVH*HD];
__device__ float g_v   [BT*NKVH*HD];
__device__ float g_y   [BT*CC];
__device__ float g_attn[BT*CC];
__device__ float g_cag [BT*CAD];
__device__ float g_cag2[BT*CAD];
__device__ float g_ca  [BT*CC];
__device__ float g_x1  [BT*CC];
__device__ float g_xm  [BT*CC];
__device__ float g_h   [(size_t)BT*FFN];
__device__ float g_h2  [(size_t)BT*FFN];
__device__ float g_gate[BT*CC];
__device__ float g_mlp [BT*CC];
__device__ float g_vit32[BT*CAD];
__device__ float g_vita[BT];
__device__ float g_vitb[BT];

// ---------------- helpers ----------------------------------------------------
__device__ __forceinline__ float geluf(float x){ return 0.5f*x*(1.0f+erff(x*0.70710678118654752f)); }
__device__ __forceinline__ float sigmf(float x){ return 1.0f/(1.0f+expf(-x)); }

// cheap split: hi = truncate-to-tf32(x) (bitmask), lo = x - hi (exact, Sterbenz).
// mma HW truncates operands to tf32 anyway, so lo's dropped low bits are lost in-HW.
__device__ __forceinline__ void splitc(float x, float& hi, float& lo){
    hi = __uint_as_float(__float_as_uint(x) & 0xFFFFE000u);
    lo = x - hi;
}

__device__ __forceinline__ void mma_tf32(float* d, const float* a, const float* b){
    asm volatile("mma.sync.aligned.m16n8k8.row.col.f32.tf32.tf32.f32 "
        "{%0,%1,%2,%3}, {%4,%5,%6,%7}, {%8,%9}, {%0,%1,%2,%3};"
        : "+f"(d[0]), "+f"(d[1]), "+f"(d[2]), "+f"(d[3])
        : "r"(__float_as_uint(a[0])), "r"(__float_as_uint(a[1])),
          "r"(__float_as_uint(a[2])), "r"(__float_as_uint(a[3])),
          "r"(__float_as_uint(b[0])), "r"(__float_as_uint(b[1])));
}

__device__ __forceinline__ void cp_async16(float* smem_dst, const float* gsrc, bool pred){
    uint32_t s = (uint32_t)__cvta_generic_to_shared(smem_dst);
    int sz = pred ? 16 : 0;
    asm volatile("cp.async.cg.shared.global [%0], [%1], 16, %2;\n" :: "r"(s), "l"(gsrc), "r"(sz));
}
#define CP_COMMIT() asm volatile("cp.async.commit_group;\n" ::: "memory")
#define CP_WAIT1()  asm volatile("cp.async.wait_group 1;\n" ::: "memory")
#define CP_WAIT0()  asm volatile("cp.async.wait_group 0;\n" ::: "memory")

// ---------------- 3xTF32 pipelined NT GEMM (round-7 proven, BN=64) -----------
// C[M,N] = A[M,K]*B[N,K]^T.  M%128==0, K%32==0, N guarded.
// BM=128 BN=64 BK=32; raw fp32 smem, cheap split in consumer; cp.async dbuf.
#define GST 36
#define TILE_A (128*GST)
#define TILE_B (64*GST)
#define GEMM_SMEM ((2*TILE_A + 2*TILE_B)*4)

template<int EPI>
__global__ void __launch_bounds__(256, 2) gemm_tf32(const float* __restrict__ A,
                                                    const float* __restrict__ Bm,
                                                    float* __restrict__ Cm,
                                                    int M, int N, int K)
{
    extern __shared__ float sm[];
    float* As[2] = { sm, sm + TILE_A };
    float* Bs[2] = { sm + 2*TILE_A, sm + 2*TILE_A + TILE_B };

    const int tid  = threadIdx.x;
    const int bm   = blockIdx.y * 128;
    const int bn   = blockIdx.x * 64;
    const int wid  = tid >> 5, lane = tid & 31;
    const int wm   = wid & 3, wn = wid >> 2;
    const int r    = lane >> 2;
    const int kq   = lane & 3;

    float acc[2][4][4];
    #pragma unroll
    for (int i = 0; i < 2; i++)
        #pragma unroll
        for (int j = 0; j < 4; j++)
            #pragma unroll
            for (int c = 0; c < 4; c++) acc[i][j][c] = 0.f;

    const int KT = K >> 5;

    {
        #pragma unroll
        for (int it = 0; it < 4; it++) {
            int g = tid + it*256;
            int m = g >> 3, kg = (g & 7) * 4;
            cp_async16(&As[0][m*GST + kg], &A[(size_t)(bm+m)*K + kg], true);
        }
        #pragma unroll
        for (int it = 0; it < 2; it++) {
            int g = tid + it*256;
            int n = g >> 3, kg = (g & 7) * 4;
            cp_async16(&Bs[0][n*GST + kg], &Bm[(size_t)(bn+n)*K + kg], bn + n < N);
        }
        CP_COMMIT();
    }

    for (int kt = 0; kt < KT; kt++) {
        if (kt + 1 < KT) {
            int k0 = (kt+1) << 5;
            int nb = (kt+1) & 1;
            #pragma unroll
            for (int it = 0; it < 4; it++) {
                int g = tid + it*256;
                int m = g >> 3, kg = (g & 7) * 4;
                cp_async16(&As[nb][m*GST + kg], &A[(size_t)(bm+m)*K + k0 + kg], true);
            }
            #pragma unroll
            for (int it = 0; it < 2; it++) {
                int g = tid + it*256;
                int n = g >> 3, kg = (g & 7) * 4;
                cp_async16(&Bs[nb][n*GST + kg], &Bm[(size_t)(bn+n)*K + k0 + kg], bn + n < N);
            }
            CP_COMMIT();
            CP_WAIT1();
        } else {
            CP_WAIT0();
        }
        __syncthreads();

        const float* Ab = As[kt & 1];
        const float* Bb = Bs[kt & 1];
        #pragma unroll
        for (int ch = 0; ch < 4; ch++) {
            const int kb = ch*8 + kq;
            float ah[2][4], al[2][4];
            #pragma unroll
            for (int mt = 0; mt < 2; mt++) {
                int row = wm*32 + mt*16 + r;
                splitc(Ab[row*GST + kb],       ah[mt][0], al[mt][0]);
                splitc(Ab[(row+8)*GST + kb],   ah[mt][1], al[mt][1]);
                splitc(Ab[row*GST + kb + 4],   ah[mt][2], al[mt][2]);
                splitc(Ab[(row+8)*GST + kb+4], ah[mt][3], al[mt][3]);
            }
            float bh[4][2], bl[4][2];
            #pragma unroll
            for (int nt = 0; nt < 4; nt++) {
                int col = wn*32 + nt*8 + r;
                splitc(Bb[col*GST + kb],     bh[nt][0], bl[nt][0]);
                splitc(Bb[col*GST + kb + 4], bh[nt][1], bl[nt][1]);
            }
            #pragma unroll
            for (int mt = 0; mt < 2; mt++)
                #pragma unroll
                for (int nt = 0; nt < 4; nt++) {
                    mma_tf32(acc[mt][nt], ah[mt], bh[nt]);
                    mma_tf32(acc[mt][nt], ah[mt], bl[nt]);
                    mma_tf32(acc[mt][nt], al[mt], bh[nt]);
                }
        }
        __syncthreads();
    }

    #pragma unroll
    for (int mt = 0; mt < 2; mt++) {
        int row0 = bm + wm*32 + mt*16 + r;
        #pragma unroll
        for (int nt = 0; nt < 4; nt++) {
            int col0 = bn + wn*32 + nt*8 + kq*2;
            #pragma unroll
            for (int c = 0; c < 4; c++) {
                int row = row0 + (c >= 2 ? 8 : 0);
                int col = col0 + (c & 1);
                if (col < N) {
                    float v = acc[mt][nt][c];
                    if (EPI == 1) { v = fmaxf(v, 0.f); v = v*v; }
                    else if (EPI == 2) { v = sigmf(v); }
                    else if (EPI == 3) { v = geluf(v); }
                    Cm[(size_t)row*N + col] = v;
                }
            }
        }
    }
}

// ---------------- rmsnorm ----------------------------------------------------
__global__ void rmsnorm_k(const float* __restrict__ in, float* __restrict__ out)
{
    __shared__ float red[256];
    int row = blockIdx.x;
    const float* r = in + (size_t)row*CC;
    float s = 0.f;
    for (int i = threadIdx.x; i < CC; i += 256) { float v = r[i]; s += v*v; }
    red[threadIdx.x] = s; __syncthreads();
    for (int st = 128; st > 0; st >>= 1) {
        if (threadIdx.x < st) red[threadIdx.x] += red[threadIdx.x+st];
        __syncthreads();
    }
    float scale = rsqrtf(red[0]/(float)CC + 1e-6f);
    for (int i = threadIdx.x; i < CC; i += 256) out[(size_t)row*CC + i] = r[i]*scale;
}

// ---------------- ve gate ----------------------------------------------------
__global__ void gatve_k(const float* __restrict__ xn, const float* __restrict__ ve,
                        const float* __restrict__ wg, float* __restrict__ v)
{
    int bt = blockIdx.x;
    int tid = threadIdx.x;
    int kv  = tid >> 6;
    float dot = 0.f;
    #pragma unroll
    for (int c = 0; c < VECH; c++) dot += xn[(size_t)bt*CC + c] * wg[kv*VECH + c];
    float gate = 3.0f * sigmf(dot);
    size_t idx = (size_t)bt*256 + tid;
    v[idx] += gate * ve[idx];
}

// ---------------- rope + per-head rmsnorm * 1.2 ------------------------------
__global__ void ropenorm_k(float* __restrict__ q, const float* __restrict__ cs,
                           const float* __restrict__ sn, int nheads)
{
    int gw   = (blockIdx.x * blockDim.x + threadIdx.x) >> 5;
    int lane = threadIdx.x & 31;
    int total = BT * nheads;
    if (gw >= total) return;
    int bt = gw / nheads, h = gw % nheads;
    int t  = bt % TT;
    float* p = q + ((size_t)bt*nheads + h)*HD;
    float x1 = p[lane], x2 = p[lane+32];
    float c = cs[t*32 + lane], s = sn[t*32 + lane];
    float o1 =  x1*c + x2*s;
    float o2 = -x1*s + x2*c;
    float ss = o1*o1 + o2*o2;
    #pragma unroll
    for (int m = 16; m > 0; m >>= 1) ss += __shfl_xor_sync(0xffffffffu, ss, m);
    float scale = rsqrtf(ss/64.f + 1e-6f) * 1.2f;
    p[lane]    = o1*scale;
    p[lane+32] = o2*scale;
}

// ---------------- flash attention with refine conv (round-2 proven) ----------
__global__ void __launch_bounds__(256) flash_k(
    const float* __restrict__ Q, const float* __restrict__ K,
    const float* __restrict__ V, const float* __restrict__ prev,
    const float* __restrict__ rw, const float* __restrict__ alphap,
    float* __restrict__ Y)
{
    extern __shared__ float sm[];
    float* Qs = sm;                 // 64*65
    float* Ks = Qs + 64*65;
    float* Vs = Ks + 64*65;
    float* Ps = Vs + 64*65;
    float* Pv = Ps + 64*65;         // 66*68
    int tid = threadIdx.x;
    int tx = tid & 15, ty = tid >> 4;
    int qb = blockIdx.x;
    int bh = blockIdx.y;            // b*NH + h
    int b = bh >> 4, h = bh & 15;
    int kvh = h >> 2;
    int q0 = qb*64;
    float alpha = alphap[0];
    float w9[9];
    #pragma unroll
    for (int i = 0; i < 9; i++) w9[i] = rw[h*9 + i];

    for (int i = tid; i < 64*16; i += 256) {
        int r = i >> 4, c4 = i & 15;
        float4 v4 = *(const float4*)&Q[((size_t)(b*TT + q0 + r)*NH + h)*HD + c4*4];
        Qs[r*65+c4*4+0]=v4.x; Qs[r*65+c4*4+1]=v4.y; Qs[r*65+c4*4+2]=v4.z; Qs[r*65+c4*4+3]=v4.w;
    }

    float m[4], l[4], o[4][4];
    #pragma unroll
    for (int i = 0; i < 4; i++) {
        m[i] = -1e30f; l[i] = 0.f;
        #pragma unroll
        for (int j = 0; j < 4; j++) o[i][j] = 0.f;
    }
    const float* pbase = prev + (size_t)bh*TT*TT;

    for (int kc = 0; kc <= qb; kc++) {
        int k0 = kc*64;
        for (int i = tid; i < 64*16; i += 256) {
            int r = i >> 4, c4 = i & 15;
            size_t base = ((size_t)(b*TT + k0 + r)*NKVH + kvh)*HD + c4*4;
            float4 k4 = *(const float4*)&K[base];
            Ks[r*65+c4*4+0]=k4.x; Ks[r*65+c4*4+1]=k4.y; Ks[r*65+c4*4+2]=k4.z; Ks[r*65+c4*4+3]=k4.w;
            float4 v4 = *(const float4*)&V[base];
            Vs[r*65+c4*4+0]=v4.x; Vs[r*65+c4*4+1]=v4.y; Vs[r*65+c4*4+2]=v4.z; Vs[r*65+c4*4+3]=v4.w;
        }
        for (int i = tid; i < 66*66; i += 256) {
            int r = i/66, c = i - r*66;
            int gq = q0-1+r, gk = k0-1+c;
            float val = 0.f;
            if (gq >= 0 && gq < TT && gk >= 0 && gk < TT) val = pbase[(size_t)gq*TT + gk];
            Pv[r*68+c] = val;
        }
        __syncthreads();

        float s[4][4];
        #pragma unroll
        for (int i = 0; i < 4; i++)
            #pragma unroll
            for (int j = 0; j < 4; j++) s[i][j] = 0.f;
        #pragma unroll 8
        for (int d = 0; d < 64; d++) {
            float a[4], bb[4];
            #pragma unroll
            for (int i = 0; i < 4; i++) a[i]  = Qs[(ty*4+i)*65 + d];
            #pragma unroll
            for (int j = 0; j < 4; j++) bb[j] = Ks[(tx*4+j)*65 + d];
            #pragma unroll
            for (int i = 0; i < 4; i++)
                #pragma unroll
                for (int j = 0; j < 4; j++) s[i][j] += a[i]*bb[j];
        }
        #pragma unroll
        for (int i = 0; i < 4; i++) {
            int lr = ty*4+i;
            #pragma unroll
            for (int j = 0; j < 4; j++) {
                int lc = tx*4+j;
                float cv = 0.f;
                #pragma unroll
                for (int di = 0; di < 3; di++)
                    #pragma unroll
                    for (int dj = 0; dj < 3; dj++)
                        cv += Pv[(lr+di)*68 + lc+dj] * w9[di*3+dj];
                float val = s[i][j]*0.125f + alpha*cv;
                if (k0+lc > q0+lr) val = -1e30f;
                s[i][j] = val;
            }
        }
        // online softmax
        float mn[4], corr[4];
        #pragma unroll
        for (int i = 0; i < 4; i++) {
            float rm = s[i][0];
            #pragma unroll
            for (int j = 1; j < 4; j++) rm = fmaxf(rm, s[i][j]);
            #pragma unroll
            for (int msk = 8; msk > 0; msk >>= 1)
                rm = fmaxf(rm, __shfl_xor_sync(0xffffffffu, rm, msk));
            mn[i] = fmaxf(m[i], rm);
            corr[i] = expf(m[i] - mn[i]);
        }
        #pragma unroll
        for (int i = 0; i < 4; i++) {
            float sum = 0.f;
            #pragma unroll
            for (int j = 0; j < 4; j++) { float p = expf(s[i][j] - mn[i]); s[i][j] = p; sum += p; }
            #pragma unroll
            for (int msk = 8; msk > 0; msk >>= 1)
                sum += __shfl_xor_sync(0xffffffffu, sum, msk);
            l[i] = l[i]*corr[i] + sum;
            m[i] = mn[i];
            #pragma unroll
            for (int j = 0; j < 4; j++) o[i][j] *= corr[i];
        }
        #pragma unroll
        for (int i = 0; i < 4; i++)
            #pragma unroll
            for (int j = 0; j < 4; j++) Ps[(ty*4+i)*65 + tx*4+j] = s[i][j];
        __syncthreads();
        #pragma unroll 8
        for (int kk = 0; kk < 64; kk++) {
            float a[4], bb[4];
            #pragma unroll
            for (int i = 0; i < 4; i++) a[i]  = Ps[(ty*4+i)*65 + kk];
            #pragma unroll
            for (int j = 0; j < 4; j++) bb[j] = Vs[kk*65 + tx*4+j];
            #pragma unroll
            for (int i = 0; i < 4; i++)
                #pragma unroll
                for (int j = 0; j < 4; j++) o[i][j] += a[i]*bb[j];
        }
        __syncthreads();
    }

    #pragma unroll
    for (int i = 0; i < 4; i++) {
        float inv = 1.f/l[i];
        #pragma unroll
        for (int j = 0; j < 4; j++)
            Y[((size_t)(b*TT + q0 + ty*4 + i)*NH + h)*HD + tx*4 + j] = o[i][j]*inv;
    }
}

// ---------------- CA channel conv (+gelu) ------------------------------------
__global__ void caconv_gelu_k(const float* __restrict__ g, const float* __restrict__ cw,
                              float* __restrict__ out)
{
    int idx = blockIdx.x*256 + threadIdx.x;
    if (idx >= BT*CAD) return;
    int c = idx & 31;
    int bt = idx >> 5;
    int t = bt & (TT-1);
    float w0 = cw[c*3], w1 = cw[c*3+1], w2 = cw[c*3+2];
    float xm1 = (t > 0)     ? g[idx-CAD] : 0.f;
    float x0  = g[idx];
    float xp1 = (t < TT-1)  ? g[idx+CAD] : 0.f;
    float h = x0 + 0.1f*(w0*xm1 + w1*x0 + w2*xp1);
    out[idx] = geluf(h);
}

// ---------------- fused 4-step FFN depthwise conv ----------------------------
__global__ void __launch_bounds__(256) ffnconv4_k(const float* __restrict__ in,
                                                  const float* __restrict__ cw,
                                                  float* __restrict__ out)
{
    __shared__ float sA[40*128];
    __shared__ float sB[40*128];
    const int tid = threadIdx.x;
    const int c0 = blockIdx.x * 128;
    const int t0 = blockIdx.y * 32;
    const int b  = blockIdx.z;
    const int c  = tid & 127;
    const int r0 = tid >> 7;

    for (int i = tid; i < 40*128; i += 256) {
        int rr = i >> 7, cc = i & 127;
        int t = t0 - 4 + rr;
        float val = 0.f;
        if (t >= 0 && t < TT) val = in[((size_t)(b*TT + t))*FFN + c0 + cc];
        sA[i] = val;
    }
    float w0 = cw[(c0+c)*3], w1 = cw[(c0+c)*3+1], w2 = cw[(c0+c)*3+2];
    __syncthreads();

    float* X = sA; float* Y2 = sB;
    #pragma unroll
    for (int it = 0; it < 4; it++) {
        for (int rr = r0; rr < 40; rr += 2) {
            int t = t0 - 4 + rr;
            float x0 = X[rr*128 + c];
            float xm = (rr > 0)  ? X[(rr-1)*128 + c] : 0.f;
            float xp = (rr < 39) ? X[(rr+1)*128 + c] : 0.f;
            float nv = x0 + 0.1f*(w0*xm + w1*x0 + w2*xp);
            if (t < 0 || t >= TT) nv = 0.f;
            Y2[rr*128 + c] = nv;
        }
        __syncthreads();
        float* tmp = X; X = Y2; Y2 = tmp;
    }
    for (int rr = 4 + r0; rr < 36; rr += 2) {
        int t = t0 - 4 + rr;
        out[((size_t)(b*TT + t))*FFN + c0 + c] = X[rr*128 + c];
    }
}

// ---------------- elementwise ------------------------------------------------
__global__ void x1_k(const float* __restrict__ x, const float* __restrict__ attn,
                     const float* __restrict__ ca, float* __restrict__ x1)
{
    size_t i = (size_t)blockIdx.x*256 + threadIdx.x;
    x1[i] = x[i] + attn[i]*(1.0f + 0.1f*tanhf(ca[i]));
}

__global__ void vitsm_k(const float* __restrict__ vin, float* __restrict__ vout)
{
    int idx = blockIdx.x*256 + threadIdx.x;
    if (idx >= BT) return;
    int b = idx >> 10, t = idx & (TT-1);
    const float* vb = vin + b*TT;
    float s = 0.f;
    #pragma unroll
    for (int o = -2; o <= 2; o++) {
        int tt = t + o;
        if (tt >= 0 && tt < TT) s += vb[tt];
    }
    s *= 0.2f;
    float v = 0.7f*vin[idx] + 0.3f*s;
    vout[idx] = (v > 0.3f) ? v : v*0.1f;
}

__global__ void final_k(const float* __restrict__ x1, const float* __restrict__ mlp,
                        const float* __restrict__ gate, const float* __restrict__ ca,
                        const float* __restrict__ vit, float* __restrict__ out)
{
    size_t i = (size_t)blockIdx.x*256 + threadIdx.x;
    int row = (int)(i >> 10);
    float m = mlp[i]*gate[i]*(1.0f + 0.1f*tanhf(ca[i]));
    out[i] = x1[i] + m*vit[row];
}

// ---------------- host -------------------------------------------------------
static void launch_gemm(const float* A, const float* B, float* C,
                        int M, int N, int K, int epi)
{
    dim3 g((N+63)/64, M/128), b(256);
    switch (epi) {
        case 0: gemm_tf32<0><<<g,b,GEMM_SMEM>>>(A,B,C,M,N,K); break;
        case 1: gemm_tf32<1><<<g,b,GEMM_SMEM>>>(A,B,C,M,N,K); break;
        case 2: gemm_tf32<2><<<g,b,GEMM_SMEM>>>(A,B,C,M,N,K); break;
        default: gemm_tf32<3><<<g,b,GEMM_SMEM>>>(A,B,C,M,N,K); break;
    }
}

#define FLASH_SMEM ((4*64*65 + 66*68)*4)

extern "C" void kernel_launch(void* const* d_in, const int* in_sizes, int n_in,
                              void* d_out, int out_size)
{
    const float* x       = (const float*)d_in[0];
    const float* ve      = (const float*)d_in[1];
    const float* cosb    = (const float*)d_in[2];
    const float* sinb    = (const float*)d_in[3];
    const float* prev    = (const float*)d_in[4];
    const float* w_q     = (const float*)d_in[5];
    const float* w_k     = (const float*)d_in[6];
    const float* w_v     = (const float*)d_in[7];
    const float* w_o     = (const float*)d_in[8];
    const float* w_veg   = (const float*)d_in[9];
    const float* refw    = (const float*)d_in[10];
    const float* ralpha  = (const float*)d_in[11];
    const float* ca_pi   = (const float*)d_in[12];
    const float* ca_cw   = (const float*)d_in[13];
    const float* ca_po   = (const float*)d_in[14];
    const float* ffn_in  = (const float*)d_in[15];
    const float* ffn_cw  = (const float*)d_in[16];
    const float* ffn_out = (const float*)d_in[17];
    const float* ffn_gate= (const float*)d_in[18];
    const float* vit_w1  = (const float*)d_in[19];
    const float* vit_w2  = (const float*)d_in[20];
    float* out = (float*)d_out;

    static bool attr_done = false;
    if (!attr_done) {
        cudaFuncSetAttribute(gemm_tf32<0>, cudaFuncAttributeMaxDynamicSharedMemorySize, GEMM_SMEM);
        cudaFuncSetAttribute(gemm_tf32<1>, cudaFuncAttributeMaxDynamicSharedMemorySize, GEMM_SMEM);
        cudaFuncSetAttribute(gemm_tf32<2>, cudaFuncAttributeMaxDynamicSharedMemorySize, GEMM_SMEM);
        cudaFuncSetAttribute(gemm_tf32<3>, cudaFuncAttributeMaxDynamicSharedMemorySize, GEMM_SMEM);
        cudaFuncSetAttribute(flash_k, cudaFuncAttributeMaxDynamicSharedMemorySize, FLASH_SMEM);
        attr_done = true;
    }

    float *xn,*q,*k,*v,*y,*attn,*cag,*cag2,*ca,*x1,*xm,*h,*h2,*gate,*mlp,*vit32,*vita,*vitb;
    cudaGetSymbolAddress((void**)&xn,   g_xn);
    cudaGetSymbolAddress((void**)&q,    g_q);
    cudaGetSymbolAddress((void**)&k,    g_k);
    cudaGetSymbolAddress((void**)&v,    g_v);
    cudaGetSymbolAddress((void**)&y,    g_y);
    cudaGetSymbolAddress((void**)&attn, g_attn);
    cudaGetSymbolAddress((void**)&cag,  g_cag);
    cudaGetSymbolAddress((void**)&cag2, g_cag2);
    cudaGetSymbolAddress((void**)&ca,   g_ca);
    cudaGetSymbolAddress((void**)&x1,   g_x1);
    cudaGetSymbolAddress((void**)&xm,   g_xm);
    cudaGetSymbolAddress((void**)&h,    g_h);
    cudaGetSymbolAddress((void**)&h2,   g_h2);
    cudaGetSymbolAddress((void**)&gate, g_gate);
    cudaGetSymbolAddress((void**)&mlp,  g_mlp);
    cudaGetSymbolAddress((void**)&vit32,g_vit32);
    cudaGetSymbolAddress((void**)&vita, g_vita);
    cudaGetSymbolAddress((void**)&vitb, g_vitb);

    rmsnorm_k<<<BT, 256>>>(x, xn);
    launch_gemm(xn, w_q, q, BT, CC, CC, 0);
    launch_gemm(xn, w_k, k, BT, NKVH*HD, CC, 0);
    launch_gemm(xn, w_v, v, BT, NKVH*HD, CC, 0);
    gatve_k<<<BT, 256>>>(xn, ve, w_veg, v);
    ropenorm_k<<<(BT*NH)/8, 256>>>(q, cosb, sinb, NH);
    ropenorm_k<<<(BT*NKVH)/8, 256>>>(k, cosb, sinb, NKVH);
    {
        dim3 g(TT/64, BB*NH);
        flash_k<<<g, 256, FLASH_SMEM>>>(q, k, v, prev, refw, ralpha, y);
    }
    launch_gemm(y, w_o, attn, BT, CC, CC, 0);
    launch_gemm(x, ca_pi, cag, BT, CAD, CC, 0);
    caconv_gelu_k<<<(BT*CAD)/256, 256>>>(cag, ca_cw, cag2);
    launch_gemm(cag2, ca_po, ca, BT, CC, CAD, 0);
    x1_k<<<(BT*CC)/256, 256>>>(x, attn, ca, x1);
    rmsnorm_k<<<BT, 256>>>(x1, xm);
    launch_gemm(xm, ffn_in, h, BT, FFN, CC, 1);
    {
        dim3 g(FFN/128, TT/32, BB);
        ffnconv4_k<<<g, 256>>>(h, ffn_cw, h2);
    }
    launch_gemm(xm, ffn_gate, gate, BT, CC, CC, 2);
    launch_gemm(h2, ffn_out, mlp, BT, CC, FFN, 0);
    launch_gemm(x1, ca_pi, cag, BT, CAD, CC, 0);
    caconv_gelu_k<<<(BT*CAD)/256, 256>>>(cag, ca_cw, cag2);
    launch_gemm(cag2, ca_po, ca, BT, CC, CAD, 0);
    launch_gemm(x1, vit_w1, vit32, BT, CAD, CC, 3);
    launch_gemm(vit32, vit_w2, vita, BT, 1, CAD, 2);
    vitsm_k<<<(BT+255)/256, 256>>>(vita, vitb);
    final_k<<<(BT*CC)/256, 256>>>(x1, mlp, gate, ca, vitb, out);
}

// round 10
// speedup vs baseline: 1.6136x; 1.0200x over previous
#include <cuda_runtime.h>
#include <math.h>
#include <stdint.h>

#define BB  4
#define TT  1024
#define CC  1024
#define NH  16
#define NKVH 4
#define HD  64
#define BT  (BB*TT)
#define FFN 4096
#define CAD 32
#define VECH 12
#define QKVW 1536

// ---------------- scratch ----------------------------------------------------
__device__ float g_xn  [BT*CC];
__device__ float g_qkv [(size_t)BT*QKVW];
__device__ float g_wqkv[QKVW*CC];
__device__ float g_y   [BT*CC];
__device__ float g_attn[BT*CC];
__device__ float g_cag [BT*CAD];
__device__ float g_cag2[BT*CAD];
__device__ float g_ca  [BT*CC];
__device__ float g_x1  [BT*CC];
__device__ float g_xm  [BT*CC];
__device__ float g_h   [(size_t)BT*FFN];
__device__ float g_h2  [(size_t)BT*FFN];
__device__ float g_gate[BT*CC];
__device__ float g_mlp [BT*CC];
__device__ float g_vit32[BT*CAD];
__device__ float g_vita[BT];
__device__ float g_vitb[BT];

// ---------------- helpers ----------------------------------------------------
__device__ __forceinline__ float geluf(float x){ return 0.5f*x*(1.0f+erff(x*0.70710678118654752f)); }
__device__ __forceinline__ float sigmf(float x){ return 1.0f/(1.0f+expf(-x)); }

__device__ __forceinline__ void splitc(float x, float& hi, float& lo){
    hi = __uint_as_float(__float_as_uint(x) & 0xFFFFE000u);
    lo = x - hi;
}

__device__ __forceinline__ void mma_tf32(float* d, const float* a, const float* b){
    asm volatile("mma.sync.aligned.m16n8k8.row.col.f32.tf32.tf32.f32 "
        "{%0,%1,%2,%3}, {%4,%5,%6,%7}, {%8,%9}, {%0,%1,%2,%3};"
        : "+f"(d[0]), "+f"(d[1]), "+f"(d[2]), "+f"(d[3])
        : "r"(__float_as_uint(a[0])), "r"(__float_as_uint(a[1])),
          "r"(__float_as_uint(a[2])), "r"(__float_as_uint(a[3])),
          "r"(__float_as_uint(b[0])), "r"(__float_as_uint(b[1])));
}

__device__ __forceinline__ void cp_async16(float* smem_dst, const float* gsrc, bool pred){
    uint32_t s = (uint32_t)__cvta_generic_to_shared(smem_dst);
    int sz = pred ? 16 : 0;
    asm volatile("cp.async.cg.shared.global [%0], [%1], 16, %2;\n" :: "r"(s), "l"(gsrc), "r"(sz));
}
#define CP_COMMIT() asm volatile("cp.async.commit_group;\n" ::: "memory")
#define CP_WAIT1()  asm volatile("cp.async.wait_group 1;\n" ::: "memory")
#define CP_WAIT0()  asm volatile("cp.async.wait_group 0;\n" ::: "memory")

// ================= 3xTF32 pipelined NT GEMM, BK=64 (K>=64, K%64==0) ==========
// C[M,N] = A[M,K]*B[N,K]^T. M%128==0, N guarded. BM=128 BN=64 BK=64.
#define GST64 68
#define TA64 (128*GST64)
#define TB64 (64*GST64)
#define GEMM_SMEM ((2*TA64 + 2*TB64)*4)

template<int EPI>
__global__ void __launch_bounds__(256, 2) gemm_tf32(const float* __restrict__ A,
                                                    const float* __restrict__ Bm,
                                                    float* __restrict__ Cm,
                                                    int M, int N, int K)
{
    extern __shared__ float sm[];
    float* As[2] = { sm, sm + TA64 };
    float* Bs[2] = { sm + 2*TA64, sm + 2*TA64 + TB64 };

    const int tid  = threadIdx.x;
    const int bm   = blockIdx.y * 128;
    const int bn   = blockIdx.x * 64;
    const int wid  = tid >> 5, lane = tid & 31;
    const int wm   = wid & 3, wn = wid >> 2;
    const int r    = lane >> 2;
    const int kq   = lane & 3;

    float acc[2][4][4];
    #pragma unroll
    for (int i = 0; i < 2; i++)
        #pragma unroll
        for (int j = 0; j < 4; j++)
            #pragma unroll
            for (int c = 0; c < 4; c++) acc[i][j][c] = 0.f;

    const int KT = K >> 6;

    {
        #pragma unroll
        for (int it = 0; it < 8; it++) {
            int g = tid + it*256;                // 0..2047
            int m = g >> 4, kg = (g & 15) * 4;
            cp_async16(&As[0][m*GST64 + kg], &A[(size_t)(bm+m)*K + kg], true);
        }
        #pragma unroll
        for (int it = 0; it < 4; it++) {
            int g = tid + it*256;                // 0..1023
            int n = g >> 4, kg = (g & 15) * 4;
            cp_async16(&Bs[0][n*GST64 + kg], &Bm[(size_t)(bn+n)*K + kg], bn + n < N);
        }
        CP_COMMIT();
    }

    for (int kt = 0; kt < KT; kt++) {
        if (kt + 1 < KT) {
            int k0 = (kt+1) << 6;
            int nb = (kt+1) & 1;
            #pragma unroll
            for (int it = 0; it < 8; it++) {
                int g = tid + it*256;
                int m = g >> 4, kg = (g & 15) * 4;
                cp_async16(&As[nb][m*GST64 + kg], &A[(size_t)(bm+m)*K + k0 + kg], true);
            }
            #pragma unroll
            for (int it = 0; it < 4; it++) {
                int g = tid + it*256;
                int n = g >> 4, kg = (g & 15) * 4;
                cp_async16(&Bs[nb][n*GST64 + kg], &Bm[(size_t)(bn+n)*K + k0 + kg], bn + n < N);
            }
            CP_COMMIT();
            CP_WAIT1();
        } else {
            CP_WAIT0();
        }
        __syncthreads();

        const float* Ab = As[kt & 1];
        const float* Bb = Bs[kt & 1];
        #pragma unroll
        for (int ch = 0; ch < 8; ch++) {
            const int kb = ch*8 + kq;
            float ah[2][4], al[2][4];
            #pragma unroll
            for (int mt = 0; mt < 2; mt++) {
                int row = wm*32 + mt*16 + r;
                splitc(Ab[row*GST64 + kb],       ah[mt][0], al[mt][0]);
                splitc(Ab[(row+8)*GST64 + kb],   ah[mt][1], al[mt][1]);
                splitc(Ab[row*GST64 + kb + 4],   ah[mt][2], al[mt][2]);
                splitc(Ab[(row+8)*GST64 + kb+4], ah[mt][3], al[mt][3]);
            }
            float bh[4][2], bl[4][2];
            #pragma unroll
            for (int nt = 0; nt < 4; nt++) {
                int col = wn*32 + nt*8 + r;
                splitc(Bb[col*GST64 + kb],     bh[nt][0], bl[nt][0]);
                splitc(Bb[col*GST64 + kb + 4], bh[nt][1], bl[nt][1]);
            }
            #pragma unroll
            for (int mt = 0; mt < 2; mt++)
                #pragma unroll
                for (int nt = 0; nt < 4; nt++) {
                    mma_tf32(acc[mt][nt], ah[mt], bh[nt]);
                    mma_tf32(acc[mt][nt], ah[mt], bl[nt]);
                    mma_tf32(acc[mt][nt], al[mt], bh[nt]);
                }
        }
        __syncthreads();
    }

    #pragma unroll
    for (int mt = 0; mt < 2; mt++) {
        int row0 = bm + wm*32 + mt*16 + r;
        #pragma unroll
        for (int nt = 0; nt < 4; nt++) {
            int col0 = bn + wn*32 + nt*8 + kq*2;
            #pragma unroll
            for (int c = 0; c < 4; c++) {
                int row = row0 + (c >= 2 ? 8 : 0);
                int col = col0 + (c & 1);
                if (col < N) {
                    float v = acc[mt][nt][c];
                    if (EPI == 1) { v = fmaxf(v, 0.f); v = v*v; }
                    else if (EPI == 2) { v = sigmf(v); }
                    else if (EPI == 3) { v = geluf(v); }
                    Cm[(size_t)row*N + col] = v;
                }
            }
        }
    }
}

// ================= BK=32 variant for K=32 call sites (round-9 proven) ========
#define GST 36
#define TILE_A (128*GST)
#define TILE_B (64*GST)
#define GEMM32_SMEM ((2*TILE_A + 2*TILE_B)*4)

template<int EPI>
__global__ void __launch_bounds__(256, 2) gemm_small(const float* __restrict__ A,
                                                     const float* __restrict__ Bm,
                                                     float* __restrict__ Cm,
                                                     int M, int N, int K)
{
    extern __shared__ float sm[];
    float* As[2] = { sm, sm + TILE_A };
    float* Bs[2] = { sm + 2*TILE_A, sm + 2*TILE_A + TILE_B };

    const int tid  = threadIdx.x;
    const int bm   = blockIdx.y * 128;
    const int bn   = blockIdx.x * 64;
    const int wid  = tid >> 5, lane = tid & 31;
    const int wm   = wid & 3, wn = wid >> 2;
    const int r    = lane >> 2;
    const int kq   = lane & 3;

    float acc[2][4][4];
    #pragma unroll
    for (int i = 0; i < 2; i++)
        #pragma unroll
        for (int j = 0; j < 4; j++)
            #pragma unroll
            for (int c = 0; c < 4; c++) acc[i][j][c] = 0.f;

    const int KT = K >> 5;

    {
        #pragma unroll
        for (int it = 0; it < 4; it++) {
            int g = tid + it*256;
            int m = g >> 3, kg = (g & 7) * 4;
            cp_async16(&As[0][m*GST + kg], &A[(size_t)(bm+m)*K + kg], true);
        }
        #pragma unroll
        for (int it = 0; it < 2; it++) {
            int g = tid + it*256;
            int n = g >> 3, kg = (g & 7) * 4;
            cp_async16(&Bs[0][n*GST + kg], &Bm[(size_t)(bn+n)*K + kg], bn + n < N);
        }
        CP_COMMIT();
    }

    for (int kt = 0; kt < KT; kt++) {
        if (kt + 1 < KT) {
            int k0 = (kt+1) << 5;
            int nb = (kt+1) & 1;
            #pragma unroll
            for (int it = 0; it < 4; it++) {
                int g = tid + it*256;
                int m = g >> 3, kg = (g & 7) * 4;
                cp_async16(&As[nb][m*GST + kg], &A[(size_t)(bm+m)*K + k0 + kg], true);
            }
            #pragma unroll
            for (int it = 0; it < 2; it++) {
                int g = tid + it*256;
                int n = g >> 3, kg = (g & 7) * 4;
                cp_async16(&Bs[nb][n*GST + kg], &Bm[(size_t)(bn+n)*K + k0 + kg], bn + n < N);
            }
            CP_COMMIT();
            CP_WAIT1();
        } else {
            CP_WAIT0();
        }
        __syncthreads();

        const float* Ab = As[kt & 1];
        const float* Bb = Bs[kt & 1];
        #pragma unroll
        for (int ch = 0; ch < 4; ch++) {
            const int kb = ch*8 + kq;
            float ah[2][4], al[2][4];
            #pragma unroll
            for (int mt = 0; mt < 2; mt++) {
                int row = wm*32 + mt*16 + r;
                splitc(Ab[row*GST + kb],       ah[mt][0], al[mt][0]);
                splitc(Ab[(row+8)*GST + kb],   ah[mt][1], al[mt][1]);
                splitc(Ab[row*GST + kb + 4],   ah[mt][2], al[mt][2]);
                splitc(Ab[(row+8)*GST + kb+4], ah[mt][3], al[mt][3]);
            }
            float bh[4][2], bl[4][2];
            #pragma unroll
            for (int nt = 0; nt < 4; nt++) {
                int col = wn*32 + nt*8 + r;
                splitc(Bb[col*GST + kb],     bh[nt][0], bl[nt][0]);
                splitc(Bb[col*GST + kb + 4], bh[nt][1], bl[nt][1]);
            }
            #pragma unroll
            for (int mt = 0; mt < 2; mt++)
                #pragma unroll
                for (int nt = 0; nt < 4; nt++) {
                    mma_tf32(acc[mt][nt], ah[mt], bh[nt]);
                    mma_tf32(acc[mt][nt], ah[mt], bl[nt]);
                    mma_tf32(acc[mt][nt], al[mt], bh[nt]);
                }
        }
        __syncthreads();
    }

    #pragma unroll
    for (int mt = 0; mt < 2; mt++) {
        int row0 = bm + wm*32 + mt*16 + r;
        #pragma unroll
        for (int nt = 0; nt < 4; nt++) {
            int col0 = bn + wn*32 + nt*8 + kq*2;
            #pragma unroll
            for (int c = 0; c < 4; c++) {
                int row = row0 + (c >= 2 ? 8 : 0);
                int col = col0 + (c & 1);
                if (col < N) {
                    float v = acc[mt][nt][c];
                    if (EPI == 1) { v = fmaxf(v, 0.f); v = v*v; }
                    else if (EPI == 2) { v = sigmf(v); }
                    else if (EPI == 3) { v = geluf(v); }
                    Cm[(size_t)row*N + col] = v;
                }
            }
        }
    }
}

// ---------------- pack w_q|w_k|w_v -> g_wqkv ---------------------------------
__global__ void packqkv_k(const float* __restrict__ wq, const float* __restrict__ wk,
                          const float* __restrict__ wv, float* __restrict__ w)
{
    int i = blockIdx.x*256 + threadIdx.x;            // float4 index
    if (i >= QKVW*CC/4) return;
    int row = i >> 8;
    int c4  = i & 255;
    float4 v;
    if (row < 1024)       v = ((const float4*)wq)[row*256 + c4];
    else if (row < 1280)  v = ((const float4*)wk)[(row-1024)*256 + c4];
    else                  v = ((const float4*)wv)[(row-1280)*256 + c4];
    ((float4*)w)[i] = v;
}

// ---------------- rmsnorm ----------------------------------------------------
__global__ void rmsnorm_k(const float* __restrict__ in, float* __restrict__ out)
{
    __shared__ float red[256];
    int row = blockIdx.x;
    const float* r = in + (size_t)row*CC;
    float s = 0.f;
    for (int i = threadIdx.x; i < CC; i += 256) { float v = r[i]; s += v*v; }
    red[threadIdx.x] = s; __syncthreads();
    for (int st = 128; st > 0; st >>= 1) {
        if (threadIdx.x < st) red[threadIdx.x] += red[threadIdx.x+st];
        __syncthreads();
    }
    float scale = rsqrtf(red[0]/(float)CC + 1e-6f);
    for (int i = threadIdx.x; i < CC; i += 256) out[(size_t)row*CC + i] = r[i]*scale;
}

// ---------------- ve gate (v slice of fused qkv) -----------------------------
__global__ void gatve_k(const float* __restrict__ xn, const float* __restrict__ ve,
                        const float* __restrict__ wg, float* __restrict__ qkv)
{
    int bt = blockIdx.x;
    int tid = threadIdx.x;              // 0..255
    int kv  = tid >> 6;
    float dot = 0.f;
    #pragma unroll
    for (int c = 0; c < VECH; c++) dot += xn[(size_t)bt*CC + c] * wg[kv*VECH + c];
    float gate = 3.0f * sigmf(dot);
    qkv[(size_t)bt*QKVW + 1280 + tid] += gate * ve[(size_t)bt*256 + tid];
}

// ---------------- rope + per-head rmsnorm * 1.2 (strided) --------------------
__global__ void ropenorm_k(float* __restrict__ base, const float* __restrict__ cs,
                           const float* __restrict__ sn, int nheads)
{
    int gw   = (blockIdx.x * blockDim.x + threadIdx.x) >> 5;
    int lane = threadIdx.x & 31;
    int total = BT * nheads;
    if (gw >= total) return;
    int bt = gw / nheads, h = gw % nheads;
    int t  = bt % TT;
    float* p = base + (size_t)bt*QKVW + h*HD;
    float x1 = p[lane], x2 = p[lane+32];
    float c = cs[t*32 + lane], s = sn[t*32 + lane];
    float o1 =  x1*c + x2*s;
    float o2 = -x1*s + x2*c;
    float ss = o1*o1 + o2*o2;
    #pragma unroll
    for (int m = 16; m > 0; m >>= 1) ss += __shfl_xor_sync(0xffffffffu, ss, m);
    float scale = rsqrtf(ss/64.f + 1e-6f) * 1.2f;
    p[lane]    = o1*scale;
    p[lane+32] = o2*scale;
}

// ---------------- flash attention with refine conv (strided QKV) -------------
__global__ void __launch_bounds__(256) flash_k(
    const float* __restrict__ QKV, const float* __restrict__ prev,
    const float* __restrict__ rw, const float* __restrict__ alphap,
    float* __restrict__ Y)
{
    extern __shared__ float sm[];
    float* Qs = sm;                 // 64*65
    float* Ks = Qs + 64*65;
    float* Vs = Ks + 64*65;
    float* Ps = Vs + 64*65;
    float* Pv = Ps + 64*65;         // 66*68
    int tid = threadIdx.x;
    int tx = tid & 15, ty = tid >> 4;
    int qb = blockIdx.x;
    int bh = blockIdx.y;            // b*NH + h
    int b = bh >> 4, h = bh & 15;
    int kvh = h >> 2;
    int q0 = qb*64;
    float alpha = alphap[0];
    float w9[9];
    #pragma unroll
    for (int i = 0; i < 9; i++) w9[i] = rw[h*9 + i];

    for (int i = tid; i < 64*16; i += 256) {
        int r = i >> 4, c4 = i & 15;
        float4 v4 = *(const float4*)&QKV[(size_t)(b*TT + q0 + r)*QKVW + h*HD + c4*4];
        Qs[r*65+c4*4+0]=v4.x; Qs[r*65+c4*4+1]=v4.y; Qs[r*65+c4*4+2]=v4.z; Qs[r*65+c4*4+3]=v4.w;
    }

    float m[4], l[4], o[4][4];
    #pragma unroll
    for (int i = 0; i < 4; i++) {
        m[i] = -1e30f; l[i] = 0.f;
        #pragma unroll
        for (int j = 0; j < 4; j++) o[i][j] = 0.f;
    }
    const float* pbase = prev + (size_t)bh*TT*TT;

    for (int kc = 0; kc <= qb; kc++) {
        int k0 = kc*64;
        for (int i = tid; i < 64*16; i += 256) {
            int r = i >> 4, c4 = i & 15;
            size_t base = (size_t)(b*TT + k0 + r)*QKVW + kvh*HD + c4*4;
            float4 k4 = *(const float4*)&QKV[1024 + base];
            Ks[r*65+c4*4+0]=k4.x; Ks[r*65+c4*4+1]=k4.y; Ks[r*65+c4*4+2]=k4.z; Ks[r*65+c4*4+3]=k4.w;
            float4 v4 = *(const float4*)&QKV[1280 + base];
            Vs[r*65+c4*4+0]=v4.x; Vs[r*65+c4*4+1]=v4.y; Vs[r*65+c4*4+2]=v4.z; Vs[r*65+c4*4+3]=v4.w;
        }
        for (int i = tid; i < 66*66; i += 256) {
            int r = i/66, c = i - r*66;
            int gq = q0-1+r, gk = k0-1+c;
            float val = 0.f;
            if (gq >= 0 && gq < TT && gk >= 0 && gk < TT) val = pbase[(size_t)gq*TT + gk];
            Pv[r*68+c] = val;
        }
        __syncthreads();

        float s[4][4];
        #pragma unroll
        for (int i = 0; i < 4; i++)
            #pragma unroll
            for (int j = 0; j < 4; j++) s[i][j] = 0.f;
        #pragma unroll 8
        for (int d = 0; d < 64; d++) {
            float a[4], bb[4];
            #pragma unroll
            for (int i = 0; i < 4; i++) a[i]  = Qs[(ty*4+i)*65 + d];
            #pragma unroll
            for (int j = 0; j < 4; j++) bb[j] = Ks[(tx*4+j)*65 + d];
            #pragma unroll
            for (int i = 0; i < 4; i++)
                #pragma unroll
                for (int j = 0; j < 4; j++) s[i][j] += a[i]*bb[j];
        }
        #pragma unroll
        for (int i = 0; i < 4; i++) {
            int lr = ty*4+i;
            #pragma unroll
            for (int j = 0; j < 4; j++) {
                int lc = tx*4+j;
                float cv = 0.f;
                #pragma unroll
                for (int di = 0; di < 3; di++)
                    #pragma unroll
                    for (int dj = 0; dj < 3; dj++)
                        cv += Pv[(lr+di)*68 + lc+dj] * w9[di*3+dj];
                float val = s[i][j]*0.125f + alpha*cv;
                if (k0+lc > q0+lr) val = -1e30f;
                s[i][j] = val;
            }
        }
        float mn[4], corr[4];
        #pragma unroll
        for (int i = 0; i < 4; i++) {
            float rm = s[i][0];
            #pragma unroll
            for (int j = 1; j < 4; j++) rm = fmaxf(rm, s[i][j]);
            #pragma unroll
            for (int msk = 8; msk > 0; msk >>= 1)
                rm = fmaxf(rm, __shfl_xor_sync(0xffffffffu, rm, msk));
            mn[i] = fmaxf(m[i], rm);
            corr[i] = expf(m[i] - mn[i]);
        }
        #pragma unroll
        for (int i = 0; i < 4; i++) {
            float sum = 0.f;
            #pragma unroll
            for (int j = 0; j < 4; j++) { float p = expf(s[i][j] - mn[i]); s[i][j] = p; sum += p; }
            #pragma unroll
            for (int msk = 8; msk > 0; msk >>= 1)
                sum += __shfl_xor_sync(0xffffffffu, sum, msk);
            l[i] = l[i]*corr[i] + sum;
            m[i] = mn[i];
            #pragma unroll
            for (int j = 0; j < 4; j++) o[i][j] *= corr[i];
        }
        #pragma unroll
        for (int i = 0; i < 4; i++)
            #pragma unroll
            for (int j = 0; j < 4; j++) Ps[(ty*4+i)*65 + tx*4+j] = s[i][j];
        __syncthreads();
        #pragma unroll 8
        for (int kk = 0; kk < 64; kk++) {
            float a[4], bb[4];
            #pragma unroll
            for (int i = 0; i < 4; i++) a[i]  = Ps[(ty*4+i)*65 + kk];
            #pragma unroll
            for (int j = 0; j < 4; j++) bb[j] = Vs[kk*65 + tx*4+j];
            #pragma unroll
            for (int i = 0; i < 4; i++)
                #pragma unroll
                for (int j = 0; j < 4; j++) o[i][j] += a[i]*bb[j];
        }
        __syncthreads();
    }

    #pragma unroll
    for (int i = 0; i < 4; i++) {
        float inv = 1.f/l[i];
        #pragma unroll
        for (int j = 0; j < 4; j++)
            Y[((size_t)(b*TT + q0 + ty*4 + i)*NH + h)*HD + tx*4 + j] = o[i][j]*inv;
    }
}

// ---------------- CA channel conv (+gelu) ------------------------------------
__global__ void caconv_gelu_k(const float* __restrict__ g, const float* __restrict__ cw,
                              float* __restrict__ out)
{
    int idx = blockIdx.x*256 + threadIdx.x;
    if (idx >= BT*CAD) return;
    int c = idx & 31;
    int bt = idx >> 5;
    int t = bt & (TT-1);
    float w0 = cw[c*3], w1 = cw[c*3+1], w2 = cw[c*3+2];
    float xm1 = (t > 0)     ? g[idx-CAD] : 0.f;
    float x0  = g[idx];
    float xp1 = (t < TT-1)  ? g[idx+CAD] : 0.f;
    float h = x0 + 0.1f*(w0*xm1 + w1*x0 + w2*xp1);
    out[idx] = geluf(h);
}

// ---------------- fused 4-step FFN depthwise conv ----------------------------
__global__ void __launch_bounds__(256) ffnconv4_k(const float* __restrict__ in,
                                                  const float* __restrict__ cw,
                                                  float* __restrict__ out)
{
    __shared__ float sA[40*128];
    __shared__ float sB[40*128];
    const int tid = threadIdx.x;
    const int c0 = blockIdx.x * 128;
    const int t0 = blockIdx.y * 32;
    const int b  = blockIdx.z;
    const int c  = tid & 127;
    const int r0 = tid >> 7;

    for (int i = tid; i < 40*128; i += 256) {
        int rr = i >> 7, cc = i & 127;
        int t = t0 - 4 + rr;
        float val = 0.f;
        if (t >= 0 && t < TT) val = in[((size_t)(b*TT + t))*FFN + c0 + cc];
        sA[i] = val;
    }
    float w0 = cw[(c0+c)*3], w1 = cw[(c0+c)*3+1], w2 = cw[(c0+c)*3+2];
    __syncthreads();

    float* X = sA; float* Y2 = sB;
    #pragma unroll
    for (int it = 0; it < 4; it++) {
        for (int rr = r0; rr < 40; rr += 2) {
            int t = t0 - 4 + rr;
            float x0 = X[rr*128 + c];
            float xm = (rr > 0)  ? X[(rr-1)*128 + c] : 0.f;
            float xp = (rr < 39) ? X[(rr+1)*128 + c] : 0.f;
            float nv = x0 + 0.1f*(w0*xm + w1*x0 + w2*xp);
            if (t < 0 || t >= TT) nv = 0.f;
            Y2[rr*128 + c] = nv;
        }
        __syncthreads();
        float* tmp = X; X = Y2; Y2 = tmp;
    }
    for (int rr = 4 + r0; rr < 36; rr += 2) {
        int t = t0 - 4 + rr;
        out[((size_t)(b*TT + t))*FFN + c0 + c] = X[rr*128 + c];
    }
}

// ---------------- elementwise ------------------------------------------------
__global__ void x1_k(const float* __restrict__ x, const float* __restrict__ attn,
                     const float* __restrict__ ca, float* __restrict__ x1)
{
    size_t i = (size_t)blockIdx.x*256 + threadIdx.x;
    x1[i] = x[i] + attn[i]*(1.0f + 0.1f*tanhf(ca[i]));
}

__global__ void vitsm_k(const float* __restrict__ vin, float* __restrict__ vout)
{
    int idx = blockIdx.x*256 + threadIdx.x;
    if (idx >= BT) return;
    int b = idx >> 10, t = idx & (TT-1);
    const float* vb = vin + b*TT;
    float s = 0.f;
    #pragma unroll
    for (int o = -2; o <= 2; o++) {
        int tt = t + o;
        if (tt >= 0 && tt < TT) s += vb[tt];
    }
    s *= 0.2f;
    float v = 0.7f*vin[idx] + 0.3f*s;
    vout[idx] = (v > 0.3f) ? v : v*0.1f;
}

__global__ void final_k(const float* __restrict__ x1, const float* __restrict__ mlp,
                        const float* __restrict__ gate, const float* __restrict__ ca,
                        const float* __restrict__ vit, float* __restrict__ out)
{
    size_t i = (size_t)blockIdx.x*256 + threadIdx.x;
    int row = (int)(i >> 10);
    float m = mlp[i]*gate[i]*(1.0f + 0.1f*tanhf(ca[i]));
    out[i] = x1[i] + m*vit[row];
}

// ---------------- host -------------------------------------------------------
static void launch_gemm(const float* A, const float* B, float* C,
                        int M, int N, int K, int epi)
{
    dim3 g((N+63)/64, M/128), b(256);
    if (K >= 64) {
        switch (epi) {
            case 0: gemm_tf32<0><<<g,b,GEMM_SMEM>>>(A,B,C,M,N,K); break;
            case 1: gemm_tf32<1><<<g,b,GEMM_SMEM>>>(A,B,C,M,N,K); break;
            case 2: gemm_tf32<2><<<g,b,GEMM_SMEM>>>(A,B,C,M,N,K); break;
            default: gemm_tf32<3><<<g,b,GEMM_SMEM>>>(A,B,C,M,N,K); break;
        }
    } else {
        switch (epi) {
            case 2: gemm_small<2><<<g,b,GEMM32_SMEM>>>(A,B,C,M,N,K); break;
            default: gemm_small<0><<<g,b,GEMM32_SMEM>>>(A,B,C,M,N,K); break;
        }
    }
}

#define FLASH_SMEM ((4*64*65 + 66*68)*4)

extern "C" void kernel_launch(void* const* d_in, const int* in_sizes, int n_in,
                              void* d_out, int out_size)
{
    const float* x       = (const float*)d_in[0];
    const float* ve      = (const float*)d_in[1];
    const float* cosb    = (const float*)d_in[2];
    const float* sinb    = (const float*)d_in[3];
    const float* prev    = (const float*)d_in[4];
    const float* w_q     = (const float*)d_in[5];
    const float* w_k     = (const float*)d_in[6];
    const float* w_v     = (const float*)d_in[7];
    const float* w_o     = (const float*)d_in[8];
    const float* w_veg   = (const float*)d_in[9];
    const float* refw    = (const float*)d_in[10];
    const float* ralpha  = (const float*)d_in[11];
    const float* ca_pi   = (const float*)d_in[12];
    const float* ca_cw   = (const float*)d_in[13];
    const float* ca_po   = (const float*)d_in[14];
    const float* ffn_in  = (const float*)d_in[15];
    const float* ffn_cw  = (const float*)d_in[16];
    const float* ffn_out = (const float*)d_in[17];
    const float* ffn_gate= (const float*)d_in[18];
    const float* vit_w1  = (const float*)d_in[19];
    const float* vit_w2  = (const float*)d_in[20];
    float* out = (float*)d_out;

    static bool attr_done = false;
    if (!attr_done) {
        cudaFuncSetAttribute(gemm_tf32<0>, cudaFuncAttributeMaxDynamicSharedMemorySize, GEMM_SMEM);
        cudaFuncSetAttribute(gemm_tf32<1>, cudaFuncAttributeMaxDynamicSharedMemorySize, GEMM_SMEM);
        cudaFuncSetAttribute(gemm_tf32<2>, cudaFuncAttributeMaxDynamicSharedMemorySize, GEMM_SMEM);
        cudaFuncSetAttribute(gemm_tf32<3>, cudaFuncAttributeMaxDynamicSharedMemorySize, GEMM_SMEM);
        cudaFuncSetAttribute(gemm_small<0>, cudaFuncAttributeMaxDynamicSharedMemorySize, GEMM32_SMEM);
        cudaFuncSetAttribute(gemm_small<2>, cudaFuncAttributeMaxDynamicSharedMemorySize, GEMM32_SMEM);
        cudaFuncSetAttribute(flash_k, cudaFuncAttributeMaxDynamicSharedMemorySize, FLASH_SMEM);
        attr_done = true;
    }

    float *xn,*qkv,*wqkv,*y,*attn,*cag,*cag2,*ca,*x1,*xm,*h,*h2,*gate,*mlp,*vit32,*vita,*vitb;
    cudaGetSymbolAddress((void**)&xn,   g_xn);
    cudaGetSymbolAddress((void**)&qkv,  g_qkv);
    cudaGetSymbolAddress((void**)&wqkv, g_wqkv);
    cudaGetSymbolAddress((void**)&y,    g_y);
    cudaGetSymbolAddress((void**)&attn, g_attn);
    cudaGetSymbolAddress((void**)&cag,  g_cag);
    cudaGetSymbolAddress((void**)&cag2, g_cag2);
    cudaGetSymbolAddress((void**)&ca,   g_ca);
    cudaGetSymbolAddress((void**)&x1,   g_x1);
    cudaGetSymbolAddress((void**)&xm,   g_xm);
    cudaGetSymbolAddress((void**)&h,    g_h);
    cudaGetSymbolAddress((void**)&h2,   g_h2);
    cudaGetSymbolAddress((void**)&gate, g_gate);
    cudaGetSymbolAddress((void**)&mlp,  g_mlp);
    cudaGetSymbolAddress((void**)&vit32,g_vit32);
    cudaGetSymbolAddress((void**)&vita, g_vita);
    cudaGetSymbolAddress((void**)&vitb, g_vitb);

    // 0. pack qkv weights (deterministic, every call)
    packqkv_k<<<(QKVW*CC/4 + 255)/256, 256>>>(w_q, w_k, w_v, wqkv);
    // 1. xn = rmsnorm(x)
    rmsnorm_k<<<BT, 256>>>(x, xn);
    // 2. fused qkv projection
    launch_gemm(xn, wqkv, qkv, BT, QKVW, CC, 0);
    // 3. ve gate on v slice
    gatve_k<<<BT, 256>>>(xn, ve, w_veg, qkv);
    // 4. rope + head rmsnorm
    ropenorm_k<<<(BT*NH)/8, 256>>>(qkv, cosb, sinb, NH);
    ropenorm_k<<<(BT*NKVH)/8, 256>>>(qkv + 1024, cosb, sinb, NKVH);
    // 5. flash attention
    {
        dim3 g(TT/64, BB*NH);
        flash_k<<<g, 256, FLASH_SMEM>>>(qkv, prev, refw, ralpha, y);
    }
    // 6. attn out
    launch_gemm(y, w_o, attn, BT, CC, CC, 0);
    // 7. ca1 (on x)
    launch_gemm(x, ca_pi, cag, BT, CAD, CC, 0);
    caconv_gelu_k<<<(BT*CAD)/256, 256>>>(cag, ca_cw, cag2);
    launch_gemm(cag2, ca_po, ca, BT, CC, CAD, 0);
    // 8. x1
    x1_k<<<(BT*CC)/256, 256>>>(x, attn, ca, x1);
    // 9. xm
    rmsnorm_k<<<BT, 256>>>(x1, xm);
    // 10. FFN
    launch_gemm(xm, ffn_in, h, BT, FFN, CC, 1);
    {
        dim3 g(FFN/128, TT/32, BB);
        ffnconv4_k<<<g, 256>>>(h, ffn_cw, h2);
    }
    launch_gemm(xm, ffn_gate, gate, BT, CC, CC, 2);
    launch_gemm(h2, ffn_out, mlp, BT, CC, FFN, 0);
    // 11. ca2 (on x1)
    launch_gemm(x1, ca_pi, cag, BT, CAD, CC, 0);
    caconv_gelu_k<<<(BT*CAD)/256, 256>>>(cag, ca_cw, cag2);
    launch_gemm(cag2, ca_po, ca, BT, CC, CAD, 0);
    // 12. vit path
    launch_gemm(x1, vit_w1, vit32, BT, CAD, CC, 3);
    launch_gemm(vit32, vit_w2, vita, BT, 1, CAD, 2);
    vitsm_k<<<(BT+255)/256, 256>>>(vita, vitb);
    // 13. final
    final_k<<<(BT*CC)/256, 256>>>(x1, mlp, gate, ca, vitb, out);
}